// round 4
// baseline (speedup 1.0000x reference)
#include <cuda_runtime.h>
#include <cstdint>

typedef unsigned long long ULL;

// ---------------- problem dims (fixed by setup_inputs) ----------------
#define T_  4
#define B_  8
#define S_  1024
#define D_  768
#define HF_ 3072
#define SD_   (S_*D_)        // 786432
#define SH_   (S_*HF_)       // 3145728
#define BSD_  (B_*SD_)       // 6291456
#define BSH_  (B_*SH_)       // 25165824
#define TBSD_ (T_*BSD_)      // 25165824
#define TBSH_ (T_*BSH_)      // 100663296
#define TBD_  (T_*B_*D_)     // 24576
#define BD_   (B_*D_)        // 6144
#define MROWS_ (T_*B_*S_)    // 32768

// Eigen gebp k-panel size hypothesis: kc = 256 (3 chains for K=768, 12 for K=3072)
#define KC_  256

// bn-stat stages
#define ST_Q   0
#define ST_V   1
#define ST_K   2
#define ST_ATT 3
#define ST_O1  4
#define ST_O2  5

// ---------------- device scratch (static, no allocation) ----------------
__device__ float g_sp  [TBSD_];
__device__ float g_q   [TBSD_];   // Q raw, then Qs spikes (in-place)
__device__ float g_k   [TBSD_];   // K raw, then Ks spikes (in-place)
__device__ float g_v   [TBSD_];   // V raw, then Vs spikes (in-place)
__device__ float g_qkvm[TBSD_];   // Vs * QKs
__device__ float g_att [TBSD_];   // QKV @ wo (raw)
__device__ float g_h   [TBSD_];
__device__ float g_sp2 [TBSD_];
__device__ float g_o1  [TBSH_];   // sp2@w1+b1 raw, then s1 spikes (in-place)
__device__ float g_o2  [TBSD_];   // s1@w2+b2 raw
__device__ float g_qkp [4*TBD_];  // QK partial sums (4 seq splits)
__device__ float g_qks [TBD_];    // QK spikes
__device__ float g_part[8*512];   // per-batch reduction partials
__device__ float g_mean [6*8];
__device__ float g_denom[6*8];    // sqrt(var + 1e-5)

// pointer table so host never queries symbol addresses (capture-safe)
__device__ float* g_ptr[9];
__global__ void k_init_ptrs() {
    if (threadIdx.x == 0 && blockIdx.x == 0) {
        g_ptr[0] = g_sp;  g_ptr[1] = g_q;    g_ptr[2] = g_k;
        g_ptr[3] = g_v;   g_ptr[4] = g_qkvm; g_ptr[5] = g_att;
        g_ptr[6] = g_sp2; g_ptr[7] = g_o1;   g_ptr[8] = g_o2;
    }
}

// ---------------- f32x2 packed helpers ----------------
// fma.rn.f32x2 / add.rn.f32x2 are bitwise two independent IEEE fp32 ops.
__device__ __forceinline__ ULL pack2(float v) {
    ULL r;
    asm("mov.b64 %0, {%1, %1};" : "=l"(r) : "f"(v));
    return r;
}
__device__ __forceinline__ void fma2(ULL& d, ULL a, ULL b) {
    asm("fma.rn.f32x2 %0, %1, %2, %0;" : "+l"(d) : "l"(a), "l"(b));
}
__device__ __forceinline__ ULL add2(ULL a, ULL b) {
    ULL r;
    asm("add.rn.f32x2 %0, %1, %2;" : "=l"(r) : "l"(a), "l"(b));
    return r;
}
__device__ __forceinline__ float2 unpack2(ULL v) {
    float2 r;
    asm("mov.b64 {%0, %1}, %2;" : "=f"(r.x), "=f"(r.y) : "l"(v));
    return r;
}

// ---------------- SGEMM: C[M,N] = A[M,K] @ B[K,N] (+ bias) ----------------
// 128x128 block tile, BK=8, 256 threads, 8x8 per-thread microtile.
// Accumulation emulates Eigen gebp k-paneling with kc=256:
//   per output: C = ((P0 + P1) + P2) ...  where each P_i is a SERIAL
//   ascending-k FFMA chain over 256 k's starting from zero.
__global__ __launch_bounds__(256, 2)
void sgemm(int aSel, const float* __restrict__ Bm, const float* __restrict__ bias,
           int cSel, int M, int N, int K)
{
    __shared__ __align__(16) float As[8][128];
    __shared__ __align__(16) float Bs[8][128];

    const float* __restrict__ A = g_ptr[aSel];
    float* __restrict__ C = g_ptr[cSel];

    const int tid = threadIdx.x;
    const int bn = blockIdx.x, bm = blockIdx.y;
    const int tx = tid & 15, ty = tid >> 4;
    const int arow = tid >> 1, acol = (tid & 1) * 4;
    const int brow = tid >> 5, bcol = (tid & 31) * 4;

    const float* Ag = A + (size_t)(bm * 128 + arow) * K + acol;
    const float* Bg = Bm + (size_t)brow * N + bn * 128 + bcol;

    ULL acc[8][4];    // outer accumulator (panel combine)
    ULL part[8][4];   // current kc-panel serial chain
#pragma unroll
    for (int i = 0; i < 8; i++)
#pragma unroll
        for (int j = 0; j < 4; j++) { acc[i][j] = 0ULL; part[i][j] = 0ULL; }

    // prefetch first tile
    float4 av = *(const float4*)(Ag);
    float4 bv = *(const float4*)(Bg);

    for (int k0 = 0; k0 < K; k0 += 8) {
        __syncthreads();
        As[acol + 0][arow] = av.x;
        As[acol + 1][arow] = av.y;
        As[acol + 2][arow] = av.z;
        As[acol + 3][arow] = av.w;
        *(float4*)&Bs[brow][bcol] = bv;
        __syncthreads();

        if (k0 + 8 < K) {
            av = *(const float4*)(Ag + k0 + 8);
            bv = *(const float4*)(Bg + (size_t)(k0 + 8) * N);
        }

#pragma unroll
        for (int kk = 0; kk < 8; kk++) {
            float a[8];
            *(float4*)(a)     = *(const float4*)&As[kk][ty * 8];
            *(float4*)(a + 4) = *(const float4*)&As[kk][ty * 8 + 4];
            ULL b2[4];
            const ULL* bp = (const ULL*)&Bs[kk][tx * 8];
            b2[0] = bp[0]; b2[1] = bp[1]; b2[2] = bp[2]; b2[3] = bp[3];
#pragma unroll
            for (int i = 0; i < 8; i++) {
                ULL a2 = pack2(a[i]);
#pragma unroll
                for (int j = 0; j < 4; j++) fma2(part[i][j], a2, b2[j]);
            }
        }

        // Eigen panel boundary: flush serial chain into outer accumulator
        if (((k0 + 8) % KC_) == 0) {
#pragma unroll
            for (int i = 0; i < 8; i++)
#pragma unroll
                for (int j = 0; j < 4; j++) {
                    acc[i][j] = add2(acc[i][j], part[i][j]);
                    part[i][j] = 0ULL;
                }
        }
    }

    // tail panel (K not multiple of KC_) — not hit for K=768/3072 but safe
#pragma unroll
    for (int i = 0; i < 8; i++)
#pragma unroll
        for (int j = 0; j < 4; j++)
            if (part[i][j] != 0ULL) acc[i][j] = add2(acc[i][j], part[i][j]);

    float bb[8];
#pragma unroll
    for (int j = 0; j < 8; j++)
        bb[j] = bias ? bias[bn * 128 + tx * 8 + j] : 0.0f;

#pragma unroll
    for (int i = 0; i < 8; i++) {
        float* Cp = C + (size_t)(bm * 128 + ty * 8 + i) * N + bn * 128 + tx * 8;
        float2 p0 = unpack2(acc[i][0]), p1 = unpack2(acc[i][1]);
        float2 p2 = unpack2(acc[i][2]), p3 = unpack2(acc[i][3]);
        *(float4*)Cp       = make_float4(p0.x + bb[0], p0.y + bb[1], p1.x + bb[2], p1.y + bb[3]);
        *(float4*)(Cp + 4) = make_float4(p2.x + bb[4], p2.y + bb[5], p3.x + bb[6], p3.y + bb[7]);
    }
}

// ---------------- IF on input x -> sp (bit-exact vs reference) ----------------
__global__ void k_ifx(const float* __restrict__ x) {
    int j = blockIdx.x * blockDim.x + threadIdx.x;
    if (j >= BSD_) return;
    float vm = 0.0f;
#pragma unroll
    for (int t = 0; t < T_; t++) {
        int idx = t * BSD_ + j;
        vm += x[idx];
        float s = (vm >= 1.0f) ? 1.0f : 0.0f;
        g_sp[idx] = s;
        vm *= (1.0f - s);
    }
}

// ---------------- BN pass A: per-batch sum -> mean ----------------
__global__ void k_redA(int sel, int SDv) {
    const float* __restrict__ X = g_ptr[sel];
    int b = blockIdx.y;
    int E = T_ * SDv;
    float s = 0.0f;
    for (int i = blockIdx.x * 256 + threadIdx.x; i < E; i += 512 * 256) {
        int t = i / SDv;
        int r = i - t * SDv;
        s += X[(size_t)(t * B_ + b) * SDv + r];
    }
    __shared__ float sh[256];
    int tid = threadIdx.x;
    sh[tid] = s; __syncthreads();
    for (int o = 128; o > 0; o >>= 1) { if (tid < o) sh[tid] += sh[tid + o]; __syncthreads(); }
    if (tid == 0) g_part[b * 512 + blockIdx.x] = sh[0];
}

__global__ void k_finA(int SDv, int stage) {
    int b = blockIdx.x, tid = threadIdx.x;
    double s = (double)g_part[b * 512 + tid] + (double)g_part[b * 512 + tid + 256];
    __shared__ double sh[256];
    sh[tid] = s; __syncthreads();
    for (int o = 128; o > 0; o >>= 1) { if (tid < o) sh[tid] += sh[tid + o]; __syncthreads(); }
    if (tid == 0) {
        float E = (float)(T_ * SDv);
        g_mean[stage * 8 + b] = __fdiv_rn((float)sh[0], E);
    }
}

// ---------------- BN pass B: per-batch sum of (x-m)^2 -> denom ----------------
__global__ void k_redB(int sel, int SDv, int stage) {
    const float* __restrict__ X = g_ptr[sel];
    int b = blockIdx.y;
    float m = g_mean[stage * 8 + b];
    int E = T_ * SDv;
    float s = 0.0f;
    for (int i = blockIdx.x * 256 + threadIdx.x; i < E; i += 512 * 256) {
        int t = i / SDv;
        int r = i - t * SDv;
        float v = X[(size_t)(t * B_ + b) * SDv + r] - m;
        s += v * v;
    }
    __shared__ float sh[256];
    int tid = threadIdx.x;
    sh[tid] = s; __syncthreads();
    for (int o = 128; o > 0; o >>= 1) { if (tid < o) sh[tid] += sh[tid + o]; __syncthreads(); }
    if (tid == 0) g_part[b * 512 + blockIdx.x] = sh[0];
}

__global__ void k_finB(int SDv, int stage) {
    int b = blockIdx.x, tid = threadIdx.x;
    double s = (double)g_part[b * 512 + tid] + (double)g_part[b * 512 + tid + 256];
    __shared__ double sh[256];
    sh[tid] = s; __syncthreads();
    for (int o = 128; o > 0; o >>= 1) { if (tid < o) sh[tid] += sh[tid + o]; __syncthreads(); }
    if (tid == 0) {
        float E = (float)(T_ * SDv);
        float var_f = __fdiv_rn((float)sh[0], E);
        g_denom[stage * 8 + b] = __fsqrt_rn(var_f + 1e-5f);
    }
}

// ---------------- fused BN + IF over Q,V,K with CARRIED membrane (Q->V->K) ----------------
__global__ void k_ifqvk() {
    int j = blockIdx.x * 256 + threadIdx.x;
    if (j >= BSD_) return;
    int b = j / SD_;
    float mq = g_mean[ST_Q * 8 + b], dq = g_denom[ST_Q * 8 + b];
    float mv = g_mean[ST_V * 8 + b], dv = g_denom[ST_V * 8 + b];
    float mk = g_mean[ST_K * 8 + b], dk = g_denom[ST_K * 8 + b];
    float vm = 0.0f;
#pragma unroll
    for (int t = 0; t < T_; t++) {
        int idx = t * BSD_ + j;
        vm += __fdiv_rn(g_q[idx] - mq, dq);
        float s = (vm >= 1.0f) ? 1.0f : 0.0f;
        g_q[idx] = s;
        vm *= (1.0f - s);
    }
#pragma unroll
    for (int t = 0; t < T_; t++) {
        int idx = t * BSD_ + j;
        vm += __fdiv_rn(g_v[idx] - mv, dv);
        float s = (vm >= 1.0f) ? 1.0f : 0.0f;
        g_v[idx] = s;
        vm *= (1.0f - s);
    }
#pragma unroll
    for (int t = 0; t < T_; t++) {
        int idx = t * BSD_ + j;
        vm += __fdiv_rn(g_k[idx] - mk, dk);
        float s = (vm >= 1.0f) ? 1.0f : 0.0f;
        g_k[idx] = s;
        vm *= (1.0f - s);
    }
}

// ---------------- QK[t,b,d] = sum_s Qs*Ks (exact integers), 4-way seq split ----------------
__global__ void k_qk() {
    int d = blockIdx.x * 256 + threadIdx.x;
    int tb = blockIdx.y;
    int sp = blockIdx.z;
    float acc = 0.0f;
    int s0 = sp * 256;
    for (int s = s0; s < s0 + 256; s++) {
        size_t idx = ((size_t)tb * S_ + s) * D_ + d;
        acc += g_q[idx] * g_k[idx];
    }
    g_qkp[sp * TBD_ + tb * D_ + d] = acc;
}

// QKs = IF(QK) over t (exact)
__global__ void k_qks() {
    int i = blockIdx.x * 256 + threadIdx.x;
    if (i >= BD_) return;
    int b = i / D_, d = i - b * D_;
    float vm = 0.0f;
#pragma unroll
    for (int t = 0; t < T_; t++) {
        int idx = (t * B_ + b) * D_ + d;
        float qk = g_qkp[idx] + g_qkp[TBD_ + idx] + g_qkp[2 * TBD_ + idx] +
                   g_qkp[3 * TBD_ + idx];
        vm += qk;
        float s = (vm >= 1.0f) ? 1.0f : 0.0f;
        g_qks[idx] = s;
        vm *= (1.0f - s);
    }
}

// QKV[t,b,s,d] = Vs * QKs[t,b,d]  (binary * binary, exact)
__global__ void k_qkvm() {
    int idx = blockIdx.x * 256 + threadIdx.x;
    if (idx >= TBSD_) return;
    int d = idx % D_;
    int tb = idx / SD_;
    g_qkvm[idx] = g_v[idx] * g_qks[tb * D_ + d];
}

// h = sp + bn(att); sp2 = IF(h)
__global__ void k_hsp2() {
    int j = blockIdx.x * 256 + threadIdx.x;
    if (j >= BSD_) return;
    int b = j / SD_;
    float m = g_mean[ST_ATT * 8 + b], dn = g_denom[ST_ATT * 8 + b];
    float vm = 0.0f;
#pragma unroll
    for (int t = 0; t < T_; t++) {
        int idx = t * BSD_ + j;
        float hval = g_sp[idx] + __fdiv_rn(g_att[idx] - m, dn);
        g_h[idx] = hval;
        vm += hval;
        float s = (vm >= 1.0f) ? 1.0f : 0.0f;
        g_sp2[idx] = s;
        vm *= (1.0f - s);
    }
}

// s1 = IF(bn(o1))  (in-place into g_o1)
__global__ void k_s1() {
    int j = blockIdx.x * 256 + threadIdx.x;
    if (j >= BSH_) return;
    int b = j / SH_;
    float m = g_mean[ST_O1 * 8 + b], dn = g_denom[ST_O1 * 8 + b];
    float vm = 0.0f;
#pragma unroll
    for (int t = 0; t < T_; t++) {
        int idx = t * BSH_ + j;
        vm += __fdiv_rn(g_o1[idx] - m, dn);
        float s = (vm >= 1.0f) ? 1.0f : 0.0f;
        g_o1[idx] = s;
        vm *= (1.0f - s);
    }
}

// out = h + bn(o2)
__global__ void k_out(float* __restrict__ out) {
    int idx = blockIdx.x * 256 + threadIdx.x;
    if (idx >= TBSD_) return;
    int b = (idx / SD_) % B_;
    float m = g_mean[ST_O2 * 8 + b], dn = g_denom[ST_O2 * 8 + b];
    out[idx] = g_h[idx] + __fdiv_rn(g_o2[idx] - m, dn);
}

// ---------------- launch ----------------
extern "C" void kernel_launch(void* const* d_in, const int* in_sizes, int n_in,
                              void* d_out, int out_size) {
    (void)in_sizes; (void)n_in; (void)out_size;
    const float* x  = (const float*)d_in[0];
    const float* wq = (const float*)d_in[1];
    const float* wk = (const float*)d_in[2];
    const float* wv = (const float*)d_in[3];
    const float* wo = (const float*)d_in[4];
    const float* w1 = (const float*)d_in[5];
    const float* b1 = (const float*)d_in[6];
    const float* w2 = (const float*)d_in[7];
    const float* b2 = (const float*)d_in[8];
    float* out = (float*)d_out;

    const int EW = 256;
    k_init_ptrs<<<1, 32>>>();

    // 1) sp = IF(x)
    k_ifx<<<BSD_ / EW, EW>>>(x);

    // 2) Q,K,V GEMMs (A = sp)
    sgemm<<<dim3(6, 256), 256>>>(0, wq, nullptr, 1, MROWS_, D_, D_);
    sgemm<<<dim3(6, 256), 256>>>(0, wk, nullptr, 2, MROWS_, D_, D_);
    sgemm<<<dim3(6, 256), 256>>>(0, wv, nullptr, 3, MROWS_, D_, D_);

    // 3) BN stats (two-pass) for Q, V, K
    k_redA<<<dim3(512, 8), 256>>>(1, SD_); k_finA<<<8, 256>>>(SD_, ST_Q);
    k_redB<<<dim3(512, 8), 256>>>(1, SD_, ST_Q); k_finB<<<8, 256>>>(SD_, ST_Q);
    k_redA<<<dim3(512, 8), 256>>>(3, SD_); k_finA<<<8, 256>>>(SD_, ST_V);
    k_redB<<<dim3(512, 8), 256>>>(3, SD_, ST_V); k_finB<<<8, 256>>>(SD_, ST_V);
    k_redA<<<dim3(512, 8), 256>>>(2, SD_); k_finA<<<8, 256>>>(SD_, ST_K);
    k_redB<<<dim3(512, 8), 256>>>(2, SD_, ST_K); k_finB<<<8, 256>>>(SD_, ST_K);

    // 4) fused BN+IF with membrane carried Q -> V -> K
    k_ifqvk<<<BSD_ / EW, EW>>>();

    // 5) QK seq-reduction + IF + QKV elementwise (all exact)
    k_qk<<<dim3(D_ / 256, T_ * B_, 4), 256>>>();
    k_qks<<<BD_ / EW, EW>>>();
    k_qkvm<<<TBSD_ / EW, EW>>>();

    // 6) att = QKV @ wo, BN stats
    sgemm<<<dim3(6, 256), 256>>>(4, wo, nullptr, 5, MROWS_, D_, D_);
    k_redA<<<dim3(512, 8), 256>>>(5, SD_); k_finA<<<8, 256>>>(SD_, ST_ATT);
    k_redB<<<dim3(512, 8), 256>>>(5, SD_, ST_ATT); k_finB<<<8, 256>>>(SD_, ST_ATT);

    // 7) h = sp + bn(att); sp2 = IF(h)
    k_hsp2<<<BSD_ / EW, EW>>>();

    // 8) o1 = sp2 @ w1 + b1; BN stats; s1 = IF(bn(o1))
    sgemm<<<dim3(24, 256), 256>>>(6, w1, b1, 7, MROWS_, HF_, D_);
    k_redA<<<dim3(512, 8), 256>>>(7, SH_); k_finA<<<8, 256>>>(SH_, ST_O1);
    k_redB<<<dim3(512, 8), 256>>>(7, SH_, ST_O1); k_finB<<<8, 256>>>(SH_, ST_O1);
    k_s1<<<BSH_ / EW, EW>>>();

    // 9) o2 = s1 @ w2 + b2; BN stats
    sgemm<<<dim3(6, 256), 256>>>(7, w2, b2, 8, MROWS_, D_, HF_);
    k_redA<<<dim3(512, 8), 256>>>(8, SD_); k_finA<<<8, 256>>>(SD_, ST_O2);
    k_redB<<<dim3(512, 8), 256>>>(8, SD_, ST_O2); k_finB<<<8, 256>>>(SD_, ST_O2);

    // 10) out = h + bn(o2)
    k_out<<<TBSD_ / EW, EW>>>(out);
}